// round 2
// baseline (speedup 1.0000x reference)
#include <cuda_runtime.h>

#define SS 100
#define BB 32
#define EW 431080

// e-column layout (concatenated param layout):
// [0,500) c1 w | [500,520) c1 b | [520,25520) c2 w | [25520,25570) c2 b
// [25570,425570) fc1 w | [425570,426070) fc1 b | [426070,431070) fc2 w | [431070,431080) fc2 b

typedef unsigned long long ull;

__device__ float g_mu[EW];
__device__ float g_sp[EW];
__device__ float g_musp[2 * EW];          // quads: [mu(2j), mu(2j+1), sp(2j), sp(2j+1)]
__device__ float g_w2[SS * 25000];        // [s][k][p][25] conv2 weights
__device__ float g_h1[SS * BB * 2880];    // [s][b][k][12][12]
__device__ float g_h2T[SS * 800 * BB];    // [s][i][b]
__device__ float g_h3P[SS * 500 * BB];    // [s][o/2][b][2] pair-interleaved
__device__ float g_logT[SS * 10 * BB];    // [s][o][b]

// ---- packed f32x2 helpers (sm_100+) --------------------------------------
__device__ __forceinline__ ull pk2(float lo, float hi) {
    ull r; asm("mov.b64 %0, {%1, %2};" : "=l"(r) : "f"(lo), "f"(hi)); return r;
}
__device__ __forceinline__ float2 upk2(ull v) {
    float2 f; asm("mov.b64 {%0, %1}, %2;" : "=f"(f.x), "=f"(f.y) : "l"(v)); return f;
}
__device__ __forceinline__ ull fma2(ull a, ull b, ull c) {
    ull d; asm("fma.rn.f32x2 %0, %1, %2, %3;" : "=l"(d) : "l"(a), "l"(b), "l"(c)); return d;
}

// ---------------------------------------------------------------------------
// K0: concat mu, precompute softplus(rho) once; also build musp quads
// ---------------------------------------------------------------------------
__global__ void k_params(const float* c1mw, const float* c1rw, const float* c1mb, const float* c1rb,
                         const float* c2mw, const float* c2rw, const float* c2mb, const float* c2rb,
                         const float* a1mw, const float* a1rw, const float* a1mb, const float* a1rb,
                         const float* a2mw, const float* a2rw, const float* a2mb, const float* a2rb) {
    int j = blockIdx.x * blockDim.x + threadIdx.x;
    if (j >= EW) return;
    float mu, rho;
    if      (j < 500)    { mu = c1mw[j];          rho = c1rw[j]; }
    else if (j < 520)    { mu = c1mb[j - 500];    rho = c1rb[j - 500]; }
    else if (j < 25520)  { mu = c2mw[j - 520];    rho = c2rw[j - 520]; }
    else if (j < 25570)  { mu = c2mb[j - 25520];  rho = c2rb[j - 25520]; }
    else if (j < 425570) { mu = a1mw[j - 25570];  rho = a1rw[j - 25570]; }
    else if (j < 426070) { mu = a1mb[j - 425570]; rho = a1rb[j - 425570]; }
    else if (j < 431070) { mu = a2mw[j - 426070]; rho = a2rw[j - 426070]; }
    else                 { mu = a2mb[j - 431070]; rho = a2rb[j - 431070]; }
    float sp = fmaxf(rho, 0.0f) + log1pf(expf(-fabsf(rho)));   // stable softplus
    g_mu[j] = mu;
    g_sp[j] = sp;
    int base = (j >> 1) * 4 + (j & 1);
    g_musp[base] = mu;
    g_musp[base + 2] = sp;
}

// ---------------------------------------------------------------------------
// K0b: materialize conv2 weights, re-laid-out [s][k][p][25]
// ---------------------------------------------------------------------------
__global__ void k_w2(const float* __restrict__ e) {
    int idx = blockIdx.x * blockDim.x + threadIdx.x;
    if (idx >= SS * 25000) return;
    int s = idx / 25000, j = idx % 25000;
    int k = j / 1250, rem = j % 1250;
    int p = rem / 25, r = rem % 25;
    int je = 520 + p * 500 + k * 25 + r;
    g_w2[idx] = g_mu[je] + g_sp[je] * e[(size_t)s * EW + je];
}

// ---------------------------------------------------------------------------
// K1: conv1 (1->20,5x5) + relu + pool -> g_h1. grid (100,32), 240 thr.
// thread = (p, pooled row Y). Row-pair f32x2 packing: acc pair = (row0,row1).
// ---------------------------------------------------------------------------
__global__ void k_conv1(const float* __restrict__ x, const float* __restrict__ e) {
    __shared__ float sx[784];
    __shared__ float sw[500];
    __shared__ float sb[20];
    int s = blockIdx.x, b = blockIdx.y, t = threadIdx.x;

    const float* xb = x + b * 784;
    for (int i = t; i < 784; i += 240) sx[i] = xb[i];
    const float* es = e + (size_t)s * EW;
    for (int i = t; i < 520; i += 240) {
        float w = g_mu[i] + g_sp[i] * es[i];
        if (i < 500) sw[i] = w; else sb[i - 500] = w;
    }
    __syncthreads();

    int p = t / 12, Y = t % 12;
    float bias = sb[p];
    const float* wp = sw + p * 25;
    float* outp = g_h1 + (size_t)(s * BB + b) * 2880 + p * 144 + Y * 12;

    #pragma unroll
    for (int half = 0; half < 2; half++) {
        int x0 = half * 12;
        ull pa[12];
        ull pb = pk2(bias, bias);
        #pragma unroll
        for (int i = 0; i < 12; i++) pa[i] = pb;
        #pragma unroll
        for (int r = 0; r < 6; r++) {
            const float4* r4 = (const float4*)(sx + (2 * Y + r) * 28 + x0);
            float4 q0 = r4[0], q1 = r4[1], q2 = r4[2], q3 = r4[3];
            float v[16] = {q0.x,q0.y,q0.z,q0.w, q1.x,q1.y,q1.z,q1.w,
                           q2.x,q2.y,q2.z,q2.w, q3.x,q3.y,q3.z,q3.w};
            ull vd[16];
            #pragma unroll
            for (int i = 0; i < 16; i++) vd[i] = pk2(v[i], v[i]);
            #pragma unroll
            for (int o = 0; o < 5; o++) {
                float w0 = (r < 5)  ? wp[r * 5 + o]       : 0.0f;
                float w1 = (r >= 1) ? wp[(r - 1) * 5 + o] : 0.0f;
                ull pw = pk2(w0, w1);
                #pragma unroll
                for (int xo = 0; xo < 12; xo++) pa[xo] = fma2(pw, vd[xo + o], pa[xo]);
            }
        }
        #pragma unroll
        for (int X = 0; X < 6; X++) {
            float2 u0 = upk2(pa[2 * X]), u1 = upk2(pa[2 * X + 1]);
            float m = fmaxf(fmaxf(u0.x, u0.y), fmaxf(u1.x, u1.y));
            outp[half * 6 + X] = fmaxf(m, 0.0f);
        }
    }
}

// ---------------------------------------------------------------------------
// K2: conv2 (20->50,5x5) + relu + pool -> g_h2T[s][i][b]. grid (100,32),
// 200 thr: thread=(p, pooled Y). Row-pair f32x2 packing; weights double-
// buffered per input channel from g_w2.
// ---------------------------------------------------------------------------
__global__ void k_conv2(const float* __restrict__ e) {
    __shared__ float sin_[2880];
    __shared__ float swk[2][1250];
    __shared__ float sb2[50];
    int s = blockIdx.x, b = blockIdx.y, t = threadIdx.x;

    const float* inb = g_h1 + (size_t)(s * BB + b) * 2880;
    for (int i = t; i < 2880; i += 200) sin_[i] = inb[i];
    const float* es = e + (size_t)s * EW;
    for (int i = t; i < 50; i += 200)
        sb2[i] = g_mu[25520 + i] + g_sp[25520 + i] * es[25520 + i];
    const float* w2s = g_w2 + (size_t)s * 25000;
    for (int i = t; i < 1250; i += 200) swk[0][i] = w2s[i];
    __syncthreads();

    int p = t / 4, Y = t % 4;
    float bias = sb2[p];
    ull pacc[8];
    ull pb = pk2(bias, bias);
    #pragma unroll
    for (int i = 0; i < 8; i++) pacc[i] = pb;

    int buf = 0;
    for (int k = 0; k < 20; k++) {
        if (k + 1 < 20)
            for (int i = t; i < 1250; i += 200) swk[buf ^ 1][i] = w2s[(k + 1) * 1250 + i];
        const float* wq = swk[buf] + p * 25;
        const float* chan = sin_ + k * 144;
        #pragma unroll
        for (int r = 0; r < 6; r++) {
            const float4* r4 = (const float4*)(chan + (2 * Y + r) * 12);
            float4 q0 = r4[0], q1 = r4[1], q2 = r4[2];
            float v[12] = {q0.x,q0.y,q0.z,q0.w, q1.x,q1.y,q1.z,q1.w,
                           q2.x,q2.y,q2.z,q2.w};
            ull vd[12];
            #pragma unroll
            for (int i = 0; i < 12; i++) vd[i] = pk2(v[i], v[i]);
            #pragma unroll
            for (int o = 0; o < 5; o++) {
                float w0 = (r < 5)  ? wq[r * 5 + o]       : 0.0f;
                float w1 = (r >= 1) ? wq[(r - 1) * 5 + o] : 0.0f;
                ull pw = pk2(w0, w1);
                #pragma unroll
                for (int xo = 0; xo < 8; xo++) pacc[xo] = fma2(pw, vd[xo + o], pacc[xo]);
            }
        }
        __syncthreads();
        buf ^= 1;
    }

    #pragma unroll
    for (int X = 0; X < 4; X++) {
        float2 u0 = upk2(pacc[2 * X]), u1 = upk2(pacc[2 * X + 1]);
        float m = fmaxf(fmaxf(u0.x, u0.y), fmaxf(u1.x, u1.y));
        g_h2T[((size_t)s * 800 + p * 16 + Y * 4 + X) * 32 + b] = fmaxf(m, 0.0f);
    }
}

// ---------------------------------------------------------------------------
// K3: fc1 (800->500) + relu -> g_h3P (pair-interleaved). grid (100,4), 256 thr.
// lane = b. musp quads give packed (mu,sp) per LDG.128; activation pairs via
// pair-interleaved smem (one LDS.64 per 2 inputs). All math in fma.f32x2.
// ---------------------------------------------------------------------------
__global__ void k_fc1(const float* __restrict__ e) {
    __shared__ float sh[160 * 32];       // pair layout: [ip][lane][2]
    int s = blockIdx.x, og = blockIdx.y, t = threadIdx.x;
    int warp = t >> 5, lane = t & 31;
    int obase = og * 125;

    ull accv[16];
    #pragma unroll
    for (int i = 0; i < 16; i++) accv[i] = 0ull;

    const float* h2s = g_h2T + (size_t)s * 25600;
    const float* es = e + (size_t)s * EW;
    const ull* shp = (const ull*)sh;

    for (int c = 0; c < 5; c++) {
        int i0 = c * 160;
        __syncthreads();
        for (int idx = t; idx < 5120; idx += 256) {
            int il = idx >> 5, bb2 = idx & 31;
            sh[(il >> 1) * 64 + bb2 * 2 + (il & 1)] = h2s[(i0 + il) * 32 + bb2];
        }
        __syncthreads();
        for (int idx = 0; idx < 16; idx++) {
            int o = obase + warp + (idx << 3);
            if (o >= obase + 125) break;
            const ulonglong2* ms = (const ulonglong2*)(g_musp + 2 * (size_t)(25570 + o * 800 + i0));
            const ull* e2 = (const ull*)(es + 25570 + (size_t)o * 800 + i0);
            ull a = accv[idx];
            #pragma unroll 4
            for (int q = 0; q < 40; q++) {          // 4 inputs per iter
                ulonglong2 m0 = ms[2 * q], m1 = ms[2 * q + 1];
                ull ea = e2[2 * q], eb = e2[2 * q + 1];
                ull w0 = fma2(m0.y, ea, m0.x);
                ull w1 = fma2(m1.y, eb, m1.x);
                a = fma2(w0, shp[(2 * q) * 32 + lane], a);
                a = fma2(w1, shp[(2 * q + 1) * 32 + lane], a);
            }
            accv[idx] = a;
        }
    }
    for (int idx = 0; idx < 16; idx++) {
        int o = obase + warp + (idx << 3);
        if (o >= obase + 125) break;
        float2 u = upk2(accv[idx]);
        float bb = g_mu[425570 + o] + g_sp[425570 + o] * es[425570 + o];
        float val = fmaxf(u.x + u.y + bb, 0.0f);
        g_h3P[(size_t)s * 16000 + (o >> 1) * 64 + lane * 2 + (o & 1)] = val;
    }
}

// ---------------------------------------------------------------------------
// K4: fc2 (500->10) -> g_logT[s][o][b]. grid 100, 320 thr (warp = o).
// ---------------------------------------------------------------------------
__global__ void k_fc2(const float* __restrict__ e) {
    int s = blockIdx.x, t = threadIdx.x;
    int o = t >> 5, lane = t & 31;
    const float* es = e + (size_t)s * EW;
    const ulonglong2* ms = (const ulonglong2*)(g_musp + 2 * (size_t)(426070 + o * 500));
    const ull* e2 = (const ull*)(es + 426070 + o * 500);
    const ull* h2 = (const ull*)(g_h3P + (size_t)s * 16000);
    ull a = 0ull;
    #pragma unroll 5
    for (int q = 0; q < 250; q++) {
        ulonglong2 m = ms[q];
        ull w = fma2(m.y, e2[q], m.x);
        a = fma2(w, h2[q * 32 + lane], a);
    }
    float2 u = upk2(a);
    float bb = g_mu[431070 + o] + g_sp[431070 + o] * es[431070 + o];
    g_logT[((size_t)s * 10 + o) * 32 + lane] = u.x + u.y + bb;
}

// ---------------------------------------------------------------------------
// K5: log_softmax over o, mean over s -> out[b][10]. grid 32, 128 thr.
// ---------------------------------------------------------------------------
__global__ void k_final(float* __restrict__ out) {
    __shared__ float red[10 * 128];
    int b = blockIdx.x, t = threadIdx.x;
    float c[10];
    if (t < SS) {
        int s = t;
        float v[10];
        float m = -1e30f;
        #pragma unroll
        for (int o = 0; o < 10; o++) {
            v[o] = g_logT[((size_t)s * 10 + o) * 32 + b];
            m = fmaxf(m, v[o]);
        }
        float se = 0.0f;
        #pragma unroll
        for (int o = 0; o < 10; o++) se += expf(v[o] - m);
        float lse = m + logf(se);
        #pragma unroll
        for (int o = 0; o < 10; o++) c[o] = v[o] - lse;
    } else {
        #pragma unroll
        for (int o = 0; o < 10; o++) c[o] = 0.0f;
    }
    #pragma unroll
    for (int o = 0; o < 10; o++) red[o * 128 + t] = c[o];
    __syncthreads();
    if (t < 10) {
        float sum = 0.0f;
        for (int i = 0; i < 128; i++) sum += red[t * 128 + i];
        out[b * 10 + t] = sum * (1.0f / SS);
    }
}

// ---------------------------------------------------------------------------
extern "C" void kernel_launch(void* const* d_in, const int* in_sizes, int n_in,
                              void* d_out, int out_size) {
    const float* x    = (const float*)d_in[0];
    const float* e    = (const float*)d_in[1];
    const float* c1mw = (const float*)d_in[2];
    const float* c1rw = (const float*)d_in[3];
    const float* c1mb = (const float*)d_in[4];
    const float* c1rb = (const float*)d_in[5];
    const float* c2mw = (const float*)d_in[6];
    const float* c2rw = (const float*)d_in[7];
    const float* c2mb = (const float*)d_in[8];
    const float* c2rb = (const float*)d_in[9];
    const float* a1mw = (const float*)d_in[10];
    const float* a1rw = (const float*)d_in[11];
    const float* a1mb = (const float*)d_in[12];
    const float* a1rb = (const float*)d_in[13];
    const float* a2mw = (const float*)d_in[14];
    const float* a2rw = (const float*)d_in[15];
    const float* a2mb = (const float*)d_in[16];
    const float* a2rb = (const float*)d_in[17];
    float* out = (float*)d_out;

    k_params<<<(EW + 255) / 256, 256>>>(c1mw, c1rw, c1mb, c1rb,
                                        c2mw, c2rw, c2mb, c2rb,
                                        a1mw, a1rw, a1mb, a1rb,
                                        a2mw, a2rw, a2mb, a2rb);
    k_w2<<<(SS * 25000 + 255) / 256, 256>>>(e);
    k_conv1<<<dim3(SS, BB), 240>>>(x, e);
    k_conv2<<<dim3(SS, BB), 200>>>(e);
    k_fc1<<<dim3(SS, 4), 256>>>(e);
    k_fc2<<<SS, 320>>>(e);
    k_final<<<BB, 128>>>(out);
}

// round 4
// speedup vs baseline: 1.1217x; 1.1217x over previous
#include <cuda_runtime.h>

#define SS 100
#define BB 32
#define EW 431080

typedef unsigned long long ull;

__device__ __align__(16) float g_mu[EW];
__device__ __align__(16) float g_sp[EW];
__device__ __align__(16) float g_musp[2 * EW];     // quads [mu0,mu1,sp0,sp1] per input pair
__device__ __align__(16) float g_w2[SS * 25600];   // [s][k][1280]: (p*25+r) in first 1250
__device__ __align__(16) float g_h1[SS * BB * 2880];   // [s][b][k][12][12]
__device__ __align__(16) float g_h2T[SS * 800 * BB];   // [s][i][b]
__device__ __align__(16) float g_h3P[SS * 500 * BB];   // [s][o/2][b][2]
__device__ __align__(16) float g_logT[SS * 10 * BB];   // [s][o][b]

// ---- packed f32x2 helpers -------------------------------------------------
__device__ __forceinline__ ull pk2(float lo, float hi) {
    ull r; asm("mov.b64 %0, {%1, %2};" : "=l"(r) : "f"(lo), "f"(hi)); return r;
}
__device__ __forceinline__ float2 upk2(ull v) {
    float2 f; asm("mov.b64 {%0, %1}, %2;" : "=f"(f.x), "=f"(f.y) : "l"(v)); return f;
}
__device__ __forceinline__ ull fma2(ull a, ull b, ull c) {
    ull d; asm("fma.rn.f32x2 %0, %1, %2, %3;" : "=l"(d) : "l"(a), "l"(b), "l"(c)); return d;
}

// ---------------------------------------------------------------------------
// K0: concat mu, softplus(rho) once; build musp quads
// ---------------------------------------------------------------------------
__global__ void k_params(const float* c1mw, const float* c1rw, const float* c1mb, const float* c1rb,
                         const float* c2mw, const float* c2rw, const float* c2mb, const float* c2rb,
                         const float* a1mw, const float* a1rw, const float* a1mb, const float* a1rb,
                         const float* a2mw, const float* a2rw, const float* a2mb, const float* a2rb) {
    int j = blockIdx.x * blockDim.x + threadIdx.x;
    if (j >= EW) return;
    float mu, rho;
    if      (j < 500)    { mu = c1mw[j];          rho = c1rw[j]; }
    else if (j < 520)    { mu = c1mb[j - 500];    rho = c1rb[j - 500]; }
    else if (j < 25520)  { mu = c2mw[j - 520];    rho = c2rw[j - 520]; }
    else if (j < 25570)  { mu = c2mb[j - 25520];  rho = c2rb[j - 25520]; }
    else if (j < 425570) { mu = a1mw[j - 25570];  rho = a1rw[j - 25570]; }
    else if (j < 426070) { mu = a1mb[j - 425570]; rho = a1rb[j - 425570]; }
    else if (j < 431070) { mu = a2mw[j - 426070]; rho = a2rw[j - 426070]; }
    else                 { mu = a2mb[j - 431070]; rho = a2rb[j - 431070]; }
    float sp = fmaxf(rho, 0.0f) + log1pf(expf(-fabsf(rho)));
    g_mu[j] = mu;
    g_sp[j] = sp;
    int base = (j >> 1) * 4 + (j & 1);
    g_musp[base] = mu;
    g_musp[base + 2] = sp;
}

// ---------------------------------------------------------------------------
// K0b: conv2 weights -> [s][k][1280] (p*25+r)
// ---------------------------------------------------------------------------
__global__ void k_w2(const float* __restrict__ e) {
    int s = blockIdx.y;
    int j = blockIdx.x * 256 + threadIdx.x;
    if (j >= 25000) return;
    int k = j / 1250, rem = j - k * 1250;
    int p = rem / 25, r = rem - p * 25;
    int je = 520 + p * 500 + k * 25 + r;
    g_w2[(size_t)s * 25600 + k * 1280 + rem] = g_mu[je] + g_sp[je] * e[(size_t)s * EW + je];
}

// ---------------------------------------------------------------------------
// K1: conv1 (1->20,5x5)+relu+pool -> g_h1. grid (100,32), 240 thr.
// ---------------------------------------------------------------------------
__global__ void k_conv1(const float* __restrict__ x, const float* __restrict__ e) {
    __shared__ __align__(16) float sx[784];
    __shared__ __align__(16) float swb[520];
    int s = blockIdx.x, b = blockIdx.y, t = threadIdx.x;

    const float4* xb4 = (const float4*)(x + b * 784);
    if (t < 196) ((float4*)sx)[t] = xb4[t];
    const float* es = e + (size_t)s * EW;
    if (t < 130) {
        float4 m = ((const float4*)g_mu)[t];
        float4 p4 = ((const float4*)g_sp)[t];
        float4 ev = ((const float4*)es)[t];
        float4 w;
        w.x = fmaf(p4.x, ev.x, m.x); w.y = fmaf(p4.y, ev.y, m.y);
        w.z = fmaf(p4.z, ev.z, m.z); w.w = fmaf(p4.w, ev.w, m.w);
        ((float4*)swb)[t] = w;
    }
    __syncthreads();

    int p = t / 12, Y = t % 12;
    float bias = swb[500 + p];
    const float* wp = swb + p * 25;
    float* outp = g_h1 + (size_t)(s * BB + b) * 2880 + p * 144 + Y * 12;

    #pragma unroll
    for (int half = 0; half < 2; half++) {
        int x0 = half * 12;
        ull pa[12];
        ull pb = pk2(bias, bias);
        #pragma unroll
        for (int i = 0; i < 12; i++) pa[i] = pb;
        #pragma unroll
        for (int r = 0; r < 6; r++) {
            const float* row = sx + (2 * Y + r) * 28 + x0;
            float v[16];
            #pragma unroll
            for (int i = 0; i < 16; i++) v[i] = row[i];
            ull vd[16];
            #pragma unroll
            for (int i = 0; i < 16; i++) vd[i] = pk2(v[i], v[i]);
            #pragma unroll
            for (int o = 0; o < 5; o++) {
                float w0 = (r < 5)  ? wp[r * 5 + o]       : 0.0f;
                float w1 = (r >= 1) ? wp[(r - 1) * 5 + o] : 0.0f;
                ull pw = pk2(w0, w1);
                #pragma unroll
                for (int xo = 0; xo < 12; xo++) pa[xo] = fma2(pw, vd[xo + o], pa[xo]);
            }
        }
        #pragma unroll
        for (int X = 0; X < 6; X++) {
            float2 u0 = upk2(pa[2 * X]), u1 = upk2(pa[2 * X + 1]);
            float m = fmaxf(fmaxf(u0.x, u0.y), fmaxf(u1.x, u1.y));
            outp[half * 6 + X] = fmaxf(m, 0.0f);
        }
    }
}

// ---------------------------------------------------------------------------
// K2: conv2 (20->50,5x5)+relu+pool. grid (100, 8 b-quads), 400 thr.
// Dynamic smem: sin4[11520] | swk[2][1280] | sb2[50]  (= 56776 B)
// ---------------------------------------------------------------------------
#define CONV2_SMEM ((4 * 2880 + 2 * 1280 + 64) * 4)
__global__ __launch_bounds__(400, 2) void k_conv2(const float* __restrict__ e) {
    extern __shared__ __align__(16) float dsm[];
    float* sin4 = dsm;                       // 11520 floats
    float* swk0 = dsm + 11520;               // 1280
    float* swk1 = dsm + 11520 + 1280;        // 1280
    float* sb2  = dsm + 11520 + 2560;        // 50
    int s = blockIdx.x, bq = blockIdx.y, t = threadIdx.x;

    const float4* src4 = (const float4*)(g_h1 + (size_t)(s * BB + bq * 4) * 2880);
    for (int i = t; i < 2880; i += 400) ((float4*)sin4)[i] = src4[i];
    const float* es = e + (size_t)s * EW;
    if (t < 50) sb2[t] = g_mu[25520 + t] + g_sp[25520 + t] * es[25520 + t];
    const float4* w4 = (const float4*)(g_w2 + (size_t)s * 25600);
    if (t < 320) ((float4*)swk0)[t] = w4[t];
    __syncthreads();

    int ih = t / 200;
    int p = (t % 200) / 4, Y = t % 4;
    float bias = sb2[p];
    ull pacc[2][8];
    ull pb = pk2(bias, bias);
    #pragma unroll
    for (int im = 0; im < 2; im++)
        #pragma unroll
        for (int i = 0; i < 8; i++) pacc[im][i] = pb;

    float* bufs[2] = {swk0, swk1};
    int buf = 0;
    for (int k = 0; k < 20; k++) {
        if (k + 1 < 20 && t < 320) ((float4*)bufs[buf ^ 1])[t] = w4[(k + 1) * 320 + t];
        const float* wq = bufs[buf] + p * 25;
        #pragma unroll
        for (int im = 0; im < 2; im++) {
            const float* chan = sin4 + (ih * 2 + im) * 2880 + k * 144;
            #pragma unroll
            for (int r = 0; r < 6; r++) {
                const float4* r4 = (const float4*)(chan + (2 * Y + r) * 12);
                float4 q0 = r4[0], q1 = r4[1], q2 = r4[2];
                float v[12] = {q0.x,q0.y,q0.z,q0.w, q1.x,q1.y,q1.z,q1.w,
                               q2.x,q2.y,q2.z,q2.w};
                ull vd[12];
                #pragma unroll
                for (int i = 0; i < 12; i++) vd[i] = pk2(v[i], v[i]);
                #pragma unroll
                for (int o = 0; o < 5; o++) {
                    float w0 = (r < 5)  ? wq[r * 5 + o]       : 0.0f;
                    float w1 = (r >= 1) ? wq[(r - 1) * 5 + o] : 0.0f;
                    ull pw = pk2(w0, w1);
                    #pragma unroll
                    for (int xo = 0; xo < 8; xo++) pacc[im][xo] = fma2(pw, vd[xo + o], pacc[im][xo]);
                }
            }
        }
        __syncthreads();
        buf ^= 1;
    }

    #pragma unroll
    for (int im = 0; im < 2; im++) {
        int b = bq * 4 + ih * 2 + im;
        #pragma unroll
        for (int X = 0; X < 4; X++) {
            float2 u0 = upk2(pacc[im][2 * X]), u1 = upk2(pacc[im][2 * X + 1]);
            float m = fmaxf(fmaxf(u0.x, u0.y), fmaxf(u1.x, u1.y));
            g_h2T[((size_t)s * 800 + p * 16 + Y * 4 + X) * 32 + b] = fmaxf(m, 0.0f);
        }
    }
}

// ---------------------------------------------------------------------------
// K3: fc1 (800->500)+relu -> g_h3P. grid (25 sg, 10 og), 256 thr (8 warps).
// Dynamic smem: sact[FC1_SG*80*64] (= 81920 B). 4 samples/warp amortize
// musp LDGs x4; e via aligned LDG.128 on shifted grid with head/tail pairs.
// ---------------------------------------------------------------------------
#define FC1_SG 4
#define FC1_SMEM (FC1_SG * 80 * 64 * 4)
__global__ __launch_bounds__(256, 2) void k_fc1(const float* __restrict__ e) {
    extern __shared__ __align__(16) float sact[];   // [ss][m][b][2]
    int sg = blockIdx.x, og = blockIdx.y, t = threadIdx.x;
    int warp = t >> 5, lane = t & 31;
    int s0 = sg * FC1_SG;
    int obase = og * 50;
    const ull* sa = (const ull*)sact;

    ull acc[7][FC1_SG];
    #pragma unroll
    for (int j = 0; j < 7; j++)
        #pragma unroll
        for (int ss = 0; ss < FC1_SG; ss++) acc[j][ss] = 0ull;

    for (int c = 0; c < 5; c++) {
        __syncthreads();
        for (int u = t; u < FC1_SG * 80 * 8; u += 256) {
            int ss = u / 640, rem = u - ss * 640;
            int m = rem >> 3, b4 = (rem & 7) << 2;
            const float* src = g_h2T + (size_t)(s0 + ss) * 25600 + (size_t)(c * 160 + 2 * m) * 32 + b4;
            float4 r0 = *(const float4*)src;
            float4 r1 = *(const float4*)(src + 32);
            float* dst = sact + ((ss * 80 + m) * 32 + b4) * 2;
            ((float4*)dst)[0] = make_float4(r0.x, r1.x, r0.y, r1.y);
            ((float4*)dst)[1] = make_float4(r0.z, r1.z, r0.w, r1.w);
        }
        __syncthreads();

        #pragma unroll
        for (int j = 0; j < 7; j++) {
            if (j * 8 + warp < 50) {
                int o = obase + j * 8 + warp;
                size_t ebase = 25570 + (size_t)o * 800 + c * 160;
                const ulonglong2* msq = ((const ulonglong2*)g_musp) + (ebase >> 1);
                const float* ep0 = e + (size_t)(s0 + 0) * EW + ebase;
                const float* ep1 = e + (size_t)(s0 + 1) * EW + ebase;
                const float* ep2 = e + (size_t)(s0 + 2) * EW + ebase;
                const float* ep3 = e + (size_t)(s0 + 3) * EW + ebase;
                const float* eps[FC1_SG] = {ep0, ep1, ep2, ep3};
                {   // head pair (local m=0)
                    ulonglong2 qh = msq[0];
                    #pragma unroll
                    for (int ss = 0; ss < FC1_SG; ss++) {
                        ull ev = *(const ull*)(eps[ss]);
                        ull w = fma2(qh.y, ev, qh.x);
                        acc[j][ss] = fma2(w, sa[(ss * 80) * 32 + lane], acc[j][ss]);
                    }
                }
                #pragma unroll 3
                for (int q = 0; q < 39; q++) {      // pairs 2q+1, 2q+2
                    ulonglong2 q1 = msq[2 * q + 1];
                    ulonglong2 q2 = msq[2 * q + 2];
                    #pragma unroll
                    for (int ss = 0; ss < FC1_SG; ss++) {
                        ulonglong2 ev = *(const ulonglong2*)(eps[ss] + 2 + 4 * q);
                        ull w1 = fma2(q1.y, ev.x, q1.x);
                        ull w2 = fma2(q2.y, ev.y, q2.x);
                        ull a = acc[j][ss];
                        a = fma2(w1, sa[(ss * 80 + 2 * q + 1) * 32 + lane], a);
                        a = fma2(w2, sa[(ss * 80 + 2 * q + 2) * 32 + lane], a);
                        acc[j][ss] = a;
                    }
                }
                {   // tail pair (local m=79)
                    ulonglong2 qt = msq[79];
                    #pragma unroll
                    for (int ss = 0; ss < FC1_SG; ss++) {
                        ull ev = *(const ull*)(eps[ss] + 158);
                        ull w = fma2(qt.y, ev, qt.x);
                        acc[j][ss] = fma2(w, sa[(ss * 80 + 79) * 32 + lane], acc[j][ss]);
                    }
                }
            }
        }
    }

    #pragma unroll
    for (int j = 0; j < 7; j++) {
        if (j * 8 + warp < 50) {
            int o = obase + j * 8 + warp;
            #pragma unroll
            for (int ss = 0; ss < FC1_SG; ss++) {
                int s = s0 + ss;
                float2 u = upk2(acc[j][ss]);
                float bb = g_mu[425570 + o] + g_sp[425570 + o] * e[(size_t)s * EW + 425570 + o];
                g_h3P[(size_t)s * 16000 + (o >> 1) * 64 + lane * 2 + (o & 1)] =
                    fmaxf(u.x + u.y + bb, 0.0f);
            }
        }
    }
}

// ---------------------------------------------------------------------------
// K4: fc2 (500->10) -> g_logT. grid 100, 320 thr (warp = o).
// ---------------------------------------------------------------------------
__global__ void k_fc2(const float* __restrict__ e) {
    int s = blockIdx.x, t = threadIdx.x;
    int o = t >> 5, lane = t & 31;
    const float* es = e + (size_t)s * EW;
    const ulonglong2* ms = (const ulonglong2*)(g_musp + 2 * (size_t)(426070 + o * 500));
    const ull* e2 = (const ull*)(es + 426070 + o * 500);
    const ull* h2 = (const ull*)(g_h3P + (size_t)s * 16000);
    ull a = 0ull;
    #pragma unroll 5
    for (int q = 0; q < 250; q++) {
        ulonglong2 m = ms[q];
        ull w = fma2(m.y, e2[q], m.x);
        a = fma2(w, h2[q * 32 + lane], a);
    }
    float2 u = upk2(a);
    float bb = g_mu[431070 + o] + g_sp[431070 + o] * es[431070 + o];
    g_logT[((size_t)s * 10 + o) * 32 + lane] = u.x + u.y + bb;
}

// ---------------------------------------------------------------------------
// K5: log_softmax + mean over s -> out[b][10]. grid 32, 128 thr.
// ---------------------------------------------------------------------------
__global__ void k_final(float* __restrict__ out) {
    __shared__ float red[10 * 128];
    int b = blockIdx.x, t = threadIdx.x;
    float c[10];
    if (t < SS) {
        float v[10];
        float m = -1e30f;
        #pragma unroll
        for (int o = 0; o < 10; o++) {
            v[o] = g_logT[((size_t)t * 10 + o) * 32 + b];
            m = fmaxf(m, v[o]);
        }
        float se = 0.0f;
        #pragma unroll
        for (int o = 0; o < 10; o++) se += expf(v[o] - m);
        float lse = m + logf(se);
        #pragma unroll
        for (int o = 0; o < 10; o++) c[o] = v[o] - lse;
    } else {
        #pragma unroll
        for (int o = 0; o < 10; o++) c[o] = 0.0f;
    }
    #pragma unroll
    for (int o = 0; o < 10; o++) red[o * 128 + t] = c[o];
    __syncthreads();
    if (t < 10) {
        float sum = 0.0f;
        for (int i = 0; i < 128; i++) sum += red[t * 128 + i];
        out[b * 10 + t] = sum * (1.0f / SS);
    }
}

// ---------------------------------------------------------------------------
extern "C" void kernel_launch(void* const* d_in, const int* in_sizes, int n_in,
                              void* d_out, int out_size) {
    const float* x    = (const float*)d_in[0];
    const float* e    = (const float*)d_in[1];
    const float* c1mw = (const float*)d_in[2];
    const float* c1rw = (const float*)d_in[3];
    const float* c1mb = (const float*)d_in[4];
    const float* c1rb = (const float*)d_in[5];
    const float* c2mw = (const float*)d_in[6];
    const float* c2rw = (const float*)d_in[7];
    const float* c2mb = (const float*)d_in[8];
    const float* c2rb = (const float*)d_in[9];
    const float* a1mw = (const float*)d_in[10];
    const float* a1rw = (const float*)d_in[11];
    const float* a1mb = (const float*)d_in[12];
    const float* a1rb = (const float*)d_in[13];
    const float* a2mw = (const float*)d_in[14];
    const float* a2rw = (const float*)d_in[15];
    const float* a2mb = (const float*)d_in[16];
    const float* a2rb = (const float*)d_in[17];
    float* out = (float*)d_out;

    cudaFuncSetAttribute(k_conv2, cudaFuncAttributeMaxDynamicSharedMemorySize, CONV2_SMEM);
    cudaFuncSetAttribute(k_fc1,   cudaFuncAttributeMaxDynamicSharedMemorySize, FC1_SMEM);

    k_params<<<(EW + 255) / 256, 256>>>(c1mw, c1rw, c1mb, c1rb,
                                        c2mw, c2rw, c2mb, c2rb,
                                        a1mw, a1rw, a1mb, a1rb,
                                        a2mw, a2rw, a2mb, a2rb);
    k_w2<<<dim3(98, SS), 256>>>(e);
    k_conv1<<<dim3(SS, BB), 240>>>(x, e);
    k_conv2<<<dim3(SS, 8), 400, CONV2_SMEM>>>(e);
    k_fc1<<<dim3(25, 10), 256, FC1_SMEM>>>(e);
    k_fc2<<<SS, 320>>>(e);
    k_final<<<BB, 128>>>(out);
}

// round 5
// speedup vs baseline: 1.2423x; 1.1075x over previous
#include <cuda_runtime.h>

#define SS 100
#define BB 32
#define EW 431080

typedef unsigned long long ull;

__device__ __align__(16) float g_mu[EW];
__device__ __align__(16) float g_sp[EW];
__device__ __align__(16) float g_musp[2 * EW];     // quads [mu0,mu1,sp0,sp1] per input pair
__device__ __align__(16) float g_w2[SS * 25600];   // [s][k][1280]: (p*25+r) in first 1250
__device__ __align__(16) float g_h1[SS * BB * 2880];   // [s][b][k][12][12]
__device__ __align__(16) float g_h2T[SS * 800 * BB];   // [s][i][b]
__device__ __align__(16) float g_h3P[SS * 500 * BB];   // [s][o/2][b][2]
__device__ __align__(16) float g_logT[SS * 10 * BB];   // [s][o][b]

// ---- packed f32x2 helpers -------------------------------------------------
__device__ __forceinline__ ull pk2(float lo, float hi) {
    ull r; asm("mov.b64 %0, {%1, %2};" : "=l"(r) : "f"(lo), "f"(hi)); return r;
}
__device__ __forceinline__ float2 upk2(ull v) {
    float2 f; asm("mov.b64 {%0, %1}, %2;" : "=f"(f.x), "=f"(f.y) : "l"(v)); return f;
}
__device__ __forceinline__ ull fma2(ull a, ull b, ull c) {
    ull d; asm("fma.rn.f32x2 %0, %1, %2, %3;" : "=l"(d) : "l"(a), "l"(b), "l"(c)); return d;
}

// ---------------------------------------------------------------------------
// K0: concat mu, softplus(rho) once; build musp quads
// ---------------------------------------------------------------------------
__global__ void k_params(const float* c1mw, const float* c1rw, const float* c1mb, const float* c1rb,
                         const float* c2mw, const float* c2rw, const float* c2mb, const float* c2rb,
                         const float* a1mw, const float* a1rw, const float* a1mb, const float* a1rb,
                         const float* a2mw, const float* a2rw, const float* a2mb, const float* a2rb) {
    int j = blockIdx.x * blockDim.x + threadIdx.x;
    if (j >= EW) return;
    float mu, rho;
    if      (j < 500)    { mu = c1mw[j];          rho = c1rw[j]; }
    else if (j < 520)    { mu = c1mb[j - 500];    rho = c1rb[j - 500]; }
    else if (j < 25520)  { mu = c2mw[j - 520];    rho = c2rw[j - 520]; }
    else if (j < 25570)  { mu = c2mb[j - 25520];  rho = c2rb[j - 25520]; }
    else if (j < 425570) { mu = a1mw[j - 25570];  rho = a1rw[j - 25570]; }
    else if (j < 426070) { mu = a1mb[j - 425570]; rho = a1rb[j - 425570]; }
    else if (j < 431070) { mu = a2mw[j - 426070]; rho = a2rw[j - 426070]; }
    else                 { mu = a2mb[j - 431070]; rho = a2rb[j - 431070]; }
    float sp = fmaxf(rho, 0.0f) + log1pf(expf(-fabsf(rho)));
    g_mu[j] = mu;
    g_sp[j] = sp;
    int base = (j >> 1) * 4 + (j & 1);
    g_musp[base] = mu;
    g_musp[base + 2] = sp;
}

// ---------------------------------------------------------------------------
// K0b: conv2 weights -> [s][k][1280] (p*25+r)
// ---------------------------------------------------------------------------
__global__ void k_w2(const float* __restrict__ e) {
    int s = blockIdx.y;
    int j = blockIdx.x * 256 + threadIdx.x;
    if (j >= 25000) return;
    int k = j / 1250, rem = j - k * 1250;
    int p = rem / 25, r = rem - p * 25;
    int je = 520 + p * 500 + k * 25 + r;
    g_w2[(size_t)s * 25600 + k * 1280 + rem] = g_mu[je] + g_sp[je] * e[(size_t)s * EW + je];
}

// ---------------------------------------------------------------------------
// K1: conv1 (1->20,5x5)+relu+pool -> g_h1. grid (100,16), 240 thr.
// Image-PAIR packed: smem input pair-interleaved, weights duplicated ->
// zero packing movs in the inner loop. 4 x-quarters bound register pressure.
// ---------------------------------------------------------------------------
__global__ void k_conv1(const float* __restrict__ x, const float* __restrict__ e) {
    __shared__ __align__(16) float sxP[1568];   // [pos][im0,im1], pos = row*28+col
    __shared__ __align__(16) float swD[1000];   // duplicated weights [p][25][2]
    __shared__ float sb1[20];
    int s = blockIdx.x, bp = blockIdx.y, t = threadIdx.x;
    int b0 = bp * 2;

    const float4* xa4 = (const float4*)(x + b0 * 784);
    const float4* xb4 = (const float4*)(x + (b0 + 1) * 784);
    if (t < 196) {
        float4 a = xa4[t], b = xb4[t];
        float4* dst = (float4*)(sxP + t * 8);
        dst[0] = make_float4(a.x, b.x, a.y, b.y);
        dst[1] = make_float4(a.z, b.z, a.w, b.w);
    }
    const float* es = e + (size_t)s * EW;
    if (t < 125) {
        float4 m = ((const float4*)g_mu)[t];
        float4 p4 = ((const float4*)g_sp)[t];
        float4 ev = ((const float4*)es)[t];
        float4 w;
        w.x = fmaf(p4.x, ev.x, m.x); w.y = fmaf(p4.y, ev.y, m.y);
        w.z = fmaf(p4.z, ev.z, m.z); w.w = fmaf(p4.w, ev.w, m.w);
        float4* dst = (float4*)(swD + t * 8);
        dst[0] = make_float4(w.x, w.x, w.y, w.y);
        dst[1] = make_float4(w.z, w.z, w.w, w.w);
    }
    if (t < 20) sb1[t] = g_mu[500 + t] + g_sp[500 + t] * es[500 + t];
    __syncthreads();

    int p = t / 12, Y = t % 12;
    float bias = sb1[p];
    ull pb = pk2(bias, bias);
    const ull* wq = (const ull*)swD + p * 25;
    float* out0 = g_h1 + (size_t)(s * BB + b0) * 2880 + p * 144 + Y * 12;
    float* out1 = out0 + 2880;

    #pragma unroll
    for (int xq = 0; xq < 4; xq++) {
        int cx0 = xq * 6;
        ull a0[6], a1[6];
        #pragma unroll
        for (int i = 0; i < 6; i++) { a0[i] = pb; a1[i] = pb; }
        #pragma unroll
        for (int rr = 0; rr < 6; rr++) {
            const ulonglong2* vp = (const ulonglong2*)(sxP + ((2 * Y + rr) * 28 + cx0) * 2);
            ull vd[10];
            #pragma unroll
            for (int i = 0; i < 5; i++) { ulonglong2 q = vp[i]; vd[2*i] = q.x; vd[2*i+1] = q.y; }
            if (rr < 5) {
                #pragma unroll
                for (int o = 0; o < 5; o++) {
                    ull wd = wq[rr * 5 + o];
                    #pragma unroll
                    for (int xo = 0; xo < 6; xo++) a0[xo] = fma2(wd, vd[xo + o], a0[xo]);
                }
            }
            if (rr >= 1) {
                #pragma unroll
                for (int o = 0; o < 5; o++) {
                    ull wd = wq[(rr - 1) * 5 + o];
                    #pragma unroll
                    for (int xo = 0; xo < 6; xo++) a1[xo] = fma2(wd, vd[xo + o], a1[xo]);
                }
            }
        }
        #pragma unroll
        for (int Xl = 0; Xl < 3; Xl++) {
            float2 u0 = upk2(a0[2 * Xl]), u1 = upk2(a0[2 * Xl + 1]);
            float2 v0 = upk2(a1[2 * Xl]), v1 = upk2(a1[2 * Xl + 1]);
            float m0 = fmaxf(fmaxf(u0.x, u1.x), fmaxf(v0.x, v1.x));
            float m1 = fmaxf(fmaxf(u0.y, u1.y), fmaxf(v0.y, v1.y));
            out0[3 * xq + Xl] = fmaxf(m0, 0.0f);
            out1[3 * xq + Xl] = fmaxf(m1, 0.0f);
        }
    }
}

// ---------------------------------------------------------------------------
// K2: conv2 (20->50,5x5)+relu+pool. grid (100, 8), 400 thr = 2 img-pairs x
// (p 0..49, Y 0..3). Image-PAIR packed: input pair-interleaved (rows padded
// to 28 floats -> conflict-free), weights duplicated (double-buffered per k).
// Zero packing movs; fma2 count at the 400/k minimum. STG.64 packed stores.
// Dynamic smem: sinP[13440] | swk[2][2560] | sb2  = 74496 B
// ---------------------------------------------------------------------------
#define CONV2_SMEM ((2 * 6720 + 2 * 2560 + 64) * 4)
__global__ __launch_bounds__(400, 2) void k_conv2(const float* __restrict__ e) {
    extern __shared__ __align__(16) float dsm[];
    float* sinP = dsm;                       // 13440: [pr][k][row(28)][x][2]
    float* swk0 = dsm + 13440;               // 2560 dup
    float* swk1 = dsm + 16000;               // 2560 dup
    float* sb2  = dsm + 18560;               // 50
    int s = blockIdx.x, bq = blockIdx.y, t = threadIdx.x;

    {   // stage 4 images as 2 interleaved pairs, row pad 24->28
        const float* base = g_h1 + (size_t)(s * BB + bq * 4) * 2880;
        for (int u = t; u < 1440; u += 400) {
            int pr = u / 720, rem = u - pr * 720;
            int k = rem / 36, rem2 = rem - k * 36;
            int row = rem2 / 3, xq = rem2 - row * 3;
            const float* s0 = base + (2 * pr) * 2880 + k * 144 + row * 12 + xq * 4;
            float4 a = *(const float4*)s0;
            float4 b = *(const float4*)(s0 + 2880);
            float* dst = sinP + pr * 6720 + k * 336 + row * 28 + xq * 8;
            ((float4*)dst)[0] = make_float4(a.x, b.x, a.y, b.y);
            ((float4*)dst)[1] = make_float4(a.z, b.z, a.w, b.w);
        }
    }
    const float* es = e + (size_t)s * EW;
    if (t < 50) sb2[t] = g_mu[25520 + t] + g_sp[25520 + t] * es[25520 + t];
    const float4* w4 = (const float4*)(g_w2 + (size_t)s * 25600);
    if (t < 320) {
        float4 w = w4[t];
        float4* d = (float4*)swk0 + 2 * t;
        d[0] = make_float4(w.x, w.x, w.y, w.y);
        d[1] = make_float4(w.z, w.z, w.w, w.w);
    }
    __syncthreads();

    int pr = t / 200, pq = t - pr * 200;
    int p = pq >> 2, Y = pq & 3;
    float bias = sb2[p];
    ull pb = pk2(bias, bias);
    ull pacc0[8], pacc1[8];
    #pragma unroll
    for (int i = 0; i < 8; i++) { pacc0[i] = pb; pacc1[i] = pb; }

    float* bufs[2] = {swk0, swk1};
    const float* sbase = sinP + pr * 6720;
    int buf = 0;
    for (int k = 0; k < 20; k++) {
        if (k + 1 < 20 && t < 320) {
            float4 w = w4[(k + 1) * 320 + t];
            float4* d = (float4*)bufs[buf ^ 1] + 2 * t;
            d[0] = make_float4(w.x, w.x, w.y, w.y);
            d[1] = make_float4(w.z, w.z, w.w, w.w);
        }
        const ull* wq = (const ull*)bufs[buf] + p * 25;
        const float* chanK = sbase + k * 336;
        #pragma unroll
        for (int rr = 0; rr < 6; rr++) {
            const ulonglong2* vp = (const ulonglong2*)(chanK + (2 * Y + rr) * 28);
            ull vd[12];
            #pragma unroll
            for (int i = 0; i < 6; i++) { ulonglong2 q = vp[i]; vd[2*i] = q.x; vd[2*i+1] = q.y; }
            if (rr < 5) {
                #pragma unroll
                for (int o = 0; o < 5; o++) {
                    ull wd = wq[rr * 5 + o];
                    #pragma unroll
                    for (int xo = 0; xo < 8; xo++) pacc0[xo] = fma2(wd, vd[xo + o], pacc0[xo]);
                }
            }
            if (rr >= 1) {
                #pragma unroll
                for (int o = 0; o < 5; o++) {
                    ull wd = wq[(rr - 1) * 5 + o];
                    #pragma unroll
                    for (int xo = 0; xo < 8; xo++) pacc1[xo] = fma2(wd, vd[xo + o], pacc1[xo]);
                }
            }
        }
        __syncthreads();
        buf ^= 1;
    }

    int b0 = bq * 4 + pr * 2;
    #pragma unroll
    for (int X = 0; X < 4; X++) {
        float2 u0 = upk2(pacc0[2 * X]), u1 = upk2(pacc0[2 * X + 1]);
        float2 v0 = upk2(pacc1[2 * X]), v1 = upk2(pacc1[2 * X + 1]);
        float m0 = fmaxf(fmaxf(u0.x, u1.x), fmaxf(v0.x, v1.x));
        float m1 = fmaxf(fmaxf(u0.y, u1.y), fmaxf(v0.y, v1.y));
        ull pv = pk2(fmaxf(m0, 0.0f), fmaxf(m1, 0.0f));
        *(ull*)&g_h2T[((size_t)s * 800 + p * 16 + Y * 4 + X) * 32 + b0] = pv;
    }
}

// ---------------------------------------------------------------------------
// K3: fc1 (800->500)+relu -> g_h3P. grid (25 sg, 10 og), 256 thr (8 warps).
// ---------------------------------------------------------------------------
#define FC1_SG 4
#define FC1_SMEM (FC1_SG * 80 * 64 * 4)
__global__ __launch_bounds__(256, 2) void k_fc1(const float* __restrict__ e) {
    extern __shared__ __align__(16) float sact[];   // [ss][m][b][2]
    int sg = blockIdx.x, og = blockIdx.y, t = threadIdx.x;
    int warp = t >> 5, lane = t & 31;
    int s0 = sg * FC1_SG;
    int obase = og * 50;
    const ull* sa = (const ull*)sact;

    ull acc[7][FC1_SG];
    #pragma unroll
    for (int j = 0; j < 7; j++)
        #pragma unroll
        for (int ss = 0; ss < FC1_SG; ss++) acc[j][ss] = 0ull;

    for (int c = 0; c < 5; c++) {
        __syncthreads();
        for (int u = t; u < FC1_SG * 80 * 8; u += 256) {
            int ss = u / 640, rem = u - ss * 640;
            int m = rem >> 3, b4 = (rem & 7) << 2;
            const float* src = g_h2T + (size_t)(s0 + ss) * 25600 + (size_t)(c * 160 + 2 * m) * 32 + b4;
            float4 r0 = *(const float4*)src;
            float4 r1 = *(const float4*)(src + 32);
            float* dst = sact + ((ss * 80 + m) * 32 + b4) * 2;
            ((float4*)dst)[0] = make_float4(r0.x, r1.x, r0.y, r1.y);
            ((float4*)dst)[1] = make_float4(r0.z, r1.z, r0.w, r1.w);
        }
        __syncthreads();

        #pragma unroll
        for (int j = 0; j < 7; j++) {
            if (j * 8 + warp < 50) {
                int o = obase + j * 8 + warp;
                size_t ebase = 25570 + (size_t)o * 800 + c * 160;
                const ulonglong2* msq = ((const ulonglong2*)g_musp) + (ebase >> 1);
                const float* ep0 = e + (size_t)(s0 + 0) * EW + ebase;
                const float* ep1 = e + (size_t)(s0 + 1) * EW + ebase;
                const float* ep2 = e + (size_t)(s0 + 2) * EW + ebase;
                const float* ep3 = e + (size_t)(s0 + 3) * EW + ebase;
                const float* eps[FC1_SG] = {ep0, ep1, ep2, ep3};
                {   // head pair (local m=0)
                    ulonglong2 qh = msq[0];
                    #pragma unroll
                    for (int ss = 0; ss < FC1_SG; ss++) {
                        ull ev = *(const ull*)(eps[ss]);
                        ull w = fma2(qh.y, ev, qh.x);
                        acc[j][ss] = fma2(w, sa[(ss * 80) * 32 + lane], acc[j][ss]);
                    }
                }
                #pragma unroll 3
                for (int q = 0; q < 39; q++) {      // pairs 2q+1, 2q+2
                    ulonglong2 q1 = msq[2 * q + 1];
                    ulonglong2 q2 = msq[2 * q + 2];
                    #pragma unroll
                    for (int ss = 0; ss < FC1_SG; ss++) {
                        ulonglong2 ev = *(const ulonglong2*)(eps[ss] + 2 + 4 * q);
                        ull w1 = fma2(q1.y, ev.x, q1.x);
                        ull w2 = fma2(q2.y, ev.y, q2.x);
                        ull a = acc[j][ss];
                        a = fma2(w1, sa[(ss * 80 + 2 * q + 1) * 32 + lane], a);
                        a = fma2(w2, sa[(ss * 80 + 2 * q + 2) * 32 + lane], a);
                        acc[j][ss] = a;
                    }
                }
                {   // tail pair (local m=79)
                    ulonglong2 qt = msq[79];
                    #pragma unroll
                    for (int ss = 0; ss < FC1_SG; ss++) {
                        ull ev = *(const ull*)(eps[ss] + 158);
                        ull w = fma2(qt.y, ev, qt.x);
                        acc[j][ss] = fma2(w, sa[(ss * 80 + 79) * 32 + lane], acc[j][ss]);
                    }
                }
            }
        }
    }

    #pragma unroll
    for (int j = 0; j < 7; j++) {
        if (j * 8 + warp < 50) {
            int o = obase + j * 8 + warp;
            #pragma unroll
            for (int ss = 0; ss < FC1_SG; ss++) {
                int s = s0 + ss;
                float2 u = upk2(acc[j][ss]);
                float bb = g_mu[425570 + o] + g_sp[425570 + o] * e[(size_t)s * EW + 425570 + o];
                g_h3P[(size_t)s * 16000 + (o >> 1) * 64 + lane * 2 + (o & 1)] =
                    fmaxf(u.x + u.y + bb, 0.0f);
            }
        }
    }
}

// ---------------------------------------------------------------------------
// K4: fc2 (500->10) -> g_logT. grid 100, 320 thr (warp = o).
// ---------------------------------------------------------------------------
__global__ void k_fc2(const float* __restrict__ e) {
    int s = blockIdx.x, t = threadIdx.x;
    int o = t >> 5, lane = t & 31;
    const float* es = e + (size_t)s * EW;
    const ulonglong2* ms = (const ulonglong2*)(g_musp + 2 * (size_t)(426070 + o * 500));
    const ull* e2 = (const ull*)(es + 426070 + o * 500);
    const ull* h2 = (const ull*)(g_h3P + (size_t)s * 16000);
    ull a = 0ull;
    #pragma unroll 5
    for (int q = 0; q < 250; q++) {
        ulonglong2 m = ms[q];
        ull w = fma2(m.y, e2[q], m.x);
        a = fma2(w, h2[q * 32 + lane], a);
    }
    float2 u = upk2(a);
    float bb = g_mu[431070 + o] + g_sp[431070 + o] * es[431070 + o];
    g_logT[((size_t)s * 10 + o) * 32 + lane] = u.x + u.y + bb;
}

// ---------------------------------------------------------------------------
// K5: log_softmax + mean over s -> out[b][10]. grid 32, 128 thr.
// ---------------------------------------------------------------------------
__global__ void k_final(float* __restrict__ out) {
    __shared__ float red[10 * 128];
    int b = blockIdx.x, t = threadIdx.x;
    float c[10];
    if (t < SS) {
        float v[10];
        float m = -1e30f;
        #pragma unroll
        for (int o = 0; o < 10; o++) {
            v[o] = g_logT[((size_t)t * 10 + o) * 32 + b];
            m = fmaxf(m, v[o]);
        }
        float se = 0.0f;
        #pragma unroll
        for (int o = 0; o < 10; o++) se += expf(v[o] - m);
        float lse = m + logf(se);
        #pragma unroll
        for (int o = 0; o < 10; o++) c[o] = v[o] - lse;
    } else {
        #pragma unroll
        for (int o = 0; o < 10; o++) c[o] = 0.0f;
    }
    #pragma unroll
    for (int o = 0; o < 10; o++) red[o * 128 + t] = c[o];
    __syncthreads();
    if (t < 10) {
        float sum = 0.0f;
        for (int i = 0; i < 128; i++) sum += red[t * 128 + i];
        out[b * 10 + t] = sum * (1.0f / SS);
    }
}

// ---------------------------------------------------------------------------
extern "C" void kernel_launch(void* const* d_in, const int* in_sizes, int n_in,
                              void* d_out, int out_size) {
    const float* x    = (const float*)d_in[0];
    const float* e    = (const float*)d_in[1];
    const float* c1mw = (const float*)d_in[2];
    const float* c1rw = (const float*)d_in[3];
    const float* c1mb = (const float*)d_in[4];
    const float* c1rb = (const float*)d_in[5];
    const float* c2mw = (const float*)d_in[6];
    const float* c2rw = (const float*)d_in[7];
    const float* c2mb = (const float*)d_in[8];
    const float* c2rb = (const float*)d_in[9];
    const float* a1mw = (const float*)d_in[10];
    const float* a1rw = (const float*)d_in[11];
    const float* a1mb = (const float*)d_in[12];
    const float* a1rb = (const float*)d_in[13];
    const float* a2mw = (const float*)d_in[14];
    const float* a2rw = (const float*)d_in[15];
    const float* a2mb = (const float*)d_in[16];
    const float* a2rb = (const float*)d_in[17];
    float* out = (float*)d_out;

    cudaFuncSetAttribute(k_conv2, cudaFuncAttributeMaxDynamicSharedMemorySize, CONV2_SMEM);
    cudaFuncSetAttribute(k_fc1,   cudaFuncAttributeMaxDynamicSharedMemorySize, FC1_SMEM);

    k_params<<<(EW + 255) / 256, 256>>>(c1mw, c1rw, c1mb, c1rb,
                                        c2mw, c2rw, c2mb, c2rb,
                                        a1mw, a1rw, a1mb, a1rb,
                                        a2mw, a2rw, a2mb, a2rb);
    k_w2<<<dim3(98, SS), 256>>>(e);
    k_conv1<<<dim3(SS, 16), 240>>>(x, e);
    k_conv2<<<dim3(SS, 8), 400, CONV2_SMEM>>>(e);
    k_fc1<<<dim3(25, 10), 256, FC1_SMEM>>>(e);
    k_fc2<<<SS, 320>>>(e);
    k_final<<<BB, 128>>>(out);
}

// round 6
// speedup vs baseline: 1.3494x; 1.0863x over previous
#include <cuda_runtime.h>

#define SS 100
#define BB 32
#define EW 431080

typedef unsigned long long ull;

__device__ __align__(16) float g_mu[EW];
__device__ __align__(16) float g_sp[EW];
__device__ __align__(16) float g_musp[2 * EW];     // quads [mu0,mu1,sp0,sp1] per input pair
__device__ __align__(16) float g_w2[SS * 25600];   // [s][k][1280]: (p*25+r) in first 1250
__device__ __align__(16) float g_h1[SS * BB * 2880];   // [s][b][k][12][12]
__device__ __align__(16) float g_h2T[SS * 800 * BB];   // [s][i][b]
__device__ __align__(16) float g_h3P[SS * 500 * BB];   // [s][o/2][b][2]
__device__ __align__(16) float g_logT[SS * 10 * BB];   // [s][o][b]

// ---- packed f32x2 helpers -------------------------------------------------
__device__ __forceinline__ ull pk2(float lo, float hi) {
    ull r; asm("mov.b64 %0, {%1, %2};" : "=l"(r) : "f"(lo), "f"(hi)); return r;
}
__device__ __forceinline__ float2 upk2(ull v) {
    float2 f; asm("mov.b64 {%0, %1}, %2;" : "=f"(f.x), "=f"(f.y) : "l"(v)); return f;
}
__device__ __forceinline__ ull fma2(ull a, ull b, ull c) {
    ull d; asm("fma.rn.f32x2 %0, %1, %2, %3;" : "=l"(d) : "l"(a), "l"(b), "l"(c)); return d;
}

// ---------------------------------------------------------------------------
// K0: concat mu, softplus(rho) once; build musp quads
// ---------------------------------------------------------------------------
__global__ void k_params(const float* c1mw, const float* c1rw, const float* c1mb, const float* c1rb,
                         const float* c2mw, const float* c2rw, const float* c2mb, const float* c2rb,
                         const float* a1mw, const float* a1rw, const float* a1mb, const float* a1rb,
                         const float* a2mw, const float* a2rw, const float* a2mb, const float* a2rb) {
    int j = blockIdx.x * blockDim.x + threadIdx.x;
    if (j >= EW) return;
    float mu, rho;
    if      (j < 500)    { mu = c1mw[j];          rho = c1rw[j]; }
    else if (j < 520)    { mu = c1mb[j - 500];    rho = c1rb[j - 500]; }
    else if (j < 25520)  { mu = c2mw[j - 520];    rho = c2rw[j - 520]; }
    else if (j < 25570)  { mu = c2mb[j - 25520];  rho = c2rb[j - 25520]; }
    else if (j < 425570) { mu = a1mw[j - 25570];  rho = a1rw[j - 25570]; }
    else if (j < 426070) { mu = a1mb[j - 425570]; rho = a1rb[j - 425570]; }
    else if (j < 431070) { mu = a2mw[j - 426070]; rho = a2rw[j - 426070]; }
    else                 { mu = a2mb[j - 431070]; rho = a2rb[j - 431070]; }
    float sp = fmaxf(rho, 0.0f) + log1pf(expf(-fabsf(rho)));
    g_mu[j] = mu;
    g_sp[j] = sp;
    int base = (j >> 1) * 4 + (j & 1);
    g_musp[base] = mu;
    g_musp[base + 2] = sp;
}

// ---------------------------------------------------------------------------
// K0b: conv2 weights -> [s][k][1280] (p*25+r)
// ---------------------------------------------------------------------------
__global__ void k_w2(const float* __restrict__ e) {
    int s = blockIdx.y;
    int j = blockIdx.x * 256 + threadIdx.x;
    if (j >= 25000) return;
    int k = j / 1250, rem = j - k * 1250;
    int p = rem / 25, r = rem - p * 25;
    int je = 520 + p * 500 + k * 25 + r;
    g_w2[(size_t)s * 25600 + k * 1280 + rem] = g_mu[je] + g_sp[je] * e[(size_t)s * EW + je];
}

// ---------------------------------------------------------------------------
// K1: conv1 (1->20,5x5)+relu+pool -> g_h1. grid (100,16), 240 thr.
// Image-PAIR packed, zero packing movs.
// ---------------------------------------------------------------------------
__global__ void k_conv1(const float* __restrict__ x, const float* __restrict__ e) {
    __shared__ __align__(16) float sxP[1568];   // [pos][im0,im1]
    __shared__ __align__(16) float swD[1000];   // duplicated weights [p][25][2]
    __shared__ float sb1[20];
    int s = blockIdx.x, bp = blockIdx.y, t = threadIdx.x;
    int b0 = bp * 2;

    const float4* xa4 = (const float4*)(x + b0 * 784);
    const float4* xb4 = (const float4*)(x + (b0 + 1) * 784);
    if (t < 196) {
        float4 a = xa4[t], b = xb4[t];
        float4* dst = (float4*)(sxP + t * 8);
        dst[0] = make_float4(a.x, b.x, a.y, b.y);
        dst[1] = make_float4(a.z, b.z, a.w, b.w);
    }
    const float* es = e + (size_t)s * EW;
    if (t < 125) {
        float4 m = ((const float4*)g_mu)[t];
        float4 p4 = ((const float4*)g_sp)[t];
        float4 ev = ((const float4*)es)[t];
        float4 w;
        w.x = fmaf(p4.x, ev.x, m.x); w.y = fmaf(p4.y, ev.y, m.y);
        w.z = fmaf(p4.z, ev.z, m.z); w.w = fmaf(p4.w, ev.w, m.w);
        float4* dst = (float4*)(swD + t * 8);
        dst[0] = make_float4(w.x, w.x, w.y, w.y);
        dst[1] = make_float4(w.z, w.z, w.w, w.w);
    }
    if (t < 20) sb1[t] = g_mu[500 + t] + g_sp[500 + t] * es[500 + t];
    __syncthreads();

    int p = t / 12, Y = t % 12;
    float bias = sb1[p];
    ull pb = pk2(bias, bias);
    const ull* wq = (const ull*)swD + p * 25;
    float* out0 = g_h1 + (size_t)(s * BB + b0) * 2880 + p * 144 + Y * 12;
    float* out1 = out0 + 2880;

    #pragma unroll
    for (int xq = 0; xq < 4; xq++) {
        int cx0 = xq * 6;
        ull a0[6], a1[6];
        #pragma unroll
        for (int i = 0; i < 6; i++) { a0[i] = pb; a1[i] = pb; }
        #pragma unroll
        for (int rr = 0; rr < 6; rr++) {
            const ulonglong2* vp = (const ulonglong2*)(sxP + ((2 * Y + rr) * 28 + cx0) * 2);
            ull vd[10];
            #pragma unroll
            for (int i = 0; i < 5; i++) { ulonglong2 q = vp[i]; vd[2*i] = q.x; vd[2*i+1] = q.y; }
            if (rr < 5) {
                #pragma unroll
                for (int o = 0; o < 5; o++) {
                    ull wd = wq[rr * 5 + o];
                    #pragma unroll
                    for (int xo = 0; xo < 6; xo++) a0[xo] = fma2(wd, vd[xo + o], a0[xo]);
                }
            }
            if (rr >= 1) {
                #pragma unroll
                for (int o = 0; o < 5; o++) {
                    ull wd = wq[(rr - 1) * 5 + o];
                    #pragma unroll
                    for (int xo = 0; xo < 6; xo++) a1[xo] = fma2(wd, vd[xo + o], a1[xo]);
                }
            }
        }
        #pragma unroll
        for (int Xl = 0; Xl < 3; Xl++) {
            float2 u0 = upk2(a0[2 * Xl]), u1 = upk2(a0[2 * Xl + 1]);
            float2 v0 = upk2(a1[2 * Xl]), v1 = upk2(a1[2 * Xl + 1]);
            float m0 = fmaxf(fmaxf(u0.x, u1.x), fmaxf(v0.x, v1.x));
            float m1 = fmaxf(fmaxf(u0.y, u1.y), fmaxf(v0.y, v1.y));
            out0[3 * xq + Xl] = fmaxf(m0, 0.0f);
            out1[3 * xq + Xl] = fmaxf(m1, 0.0f);
        }
    }
}

// ---------------------------------------------------------------------------
// K2: conv2 (20->50,5x5)+relu+pool. grid (100, 8), 400 thr. Image-PAIR packed.
// k-CHUNKED weight staging: 5 channels per barrier (8 barriers total, all
// threads stage, 5-k uninterrupted compute windows).
// Dynamic smem: sinP[13440] | swc[12800] | sb2[64] = 105216 B
// ---------------------------------------------------------------------------
#define CONV2_SMEM ((13440 + 12800 + 64) * 4)
__global__ __launch_bounds__(400, 2) void k_conv2(const float* __restrict__ e) {
    extern __shared__ __align__(16) float dsm[];
    float* sinP = dsm;                       // 13440: [pr][k][row(28)][x][2]
    float* swc  = dsm + 13440;               // 12800: 5k x [p][25][2] dup (+pad)
    float* sb2  = dsm + 26240;               // 50
    int s = blockIdx.x, bq = blockIdx.y, t = threadIdx.x;

    {   // stage 4 images as 2 interleaved pairs, row pad 24->28
        const float* base = g_h1 + (size_t)(s * BB + bq * 4) * 2880;
        for (int u = t; u < 1440; u += 400) {
            int pr = u / 720, rem = u - pr * 720;
            int k = rem / 36, rem2 = rem - k * 36;
            int row = rem2 / 3, xq = rem2 - row * 3;
            const float* s0 = base + (2 * pr) * 2880 + k * 144 + row * 12 + xq * 4;
            float4 a = *(const float4*)s0;
            float4 b = *(const float4*)(s0 + 2880);
            float* dst = sinP + pr * 6720 + k * 336 + row * 28 + xq * 8;
            ((float4*)dst)[0] = make_float4(a.x, b.x, a.y, b.y);
            ((float4*)dst)[1] = make_float4(a.z, b.z, a.w, b.w);
        }
    }
    const float* es = e + (size_t)s * EW;
    if (t < 50) sb2[t] = g_mu[25520 + t] + g_sp[25520 + t] * es[25520 + t];

    int pr = t / 200, pq = t - pr * 200;
    int p = pq >> 2, Y = pq & 3;
    float bias = sb2 != 0 ? 0.0f : 0.0f;  // placeholder; real bias read after sync
    ull pacc0[8], pacc1[8];

    const float4* w4 = (const float4*)(g_w2 + (size_t)s * 25600);
    const float* sbase = sinP + pr * 6720;

    // init accs after first sync (bias needs sb2 visible)
    bool first = true;
    for (int kc = 0; kc < 4; kc++) {
        __syncthreads();
        // stage 5 k-channels of duplicated weights: 1600 float4 reads
        for (int u = t; u < 1600; u += 400) {
            float4 w = w4[kc * 1600 + u];
            int kl = u / 320, rem = u - kl * 320;
            float4* d = (float4*)(swc + kl * 2560) + 2 * rem;
            d[0] = make_float4(w.x, w.x, w.y, w.y);
            d[1] = make_float4(w.z, w.z, w.w, w.w);
        }
        __syncthreads();
        if (first) {
            first = false;
            ull pb = pk2(sb2[p], sb2[p]);
            #pragma unroll
            for (int i = 0; i < 8; i++) { pacc0[i] = pb; pacc1[i] = pb; }
        }
        #pragma unroll
        for (int kl = 0; kl < 5; kl++) {
            int k = kc * 5 + kl;
            const ull* wq = (const ull*)(swc + kl * 2560) + p * 25;
            const float* chanK = sbase + k * 336;
            #pragma unroll
            for (int rr = 0; rr < 6; rr++) {
                const ulonglong2* vp = (const ulonglong2*)(chanK + (2 * Y + rr) * 28);
                ull vd[12];
                #pragma unroll
                for (int i = 0; i < 6; i++) { ulonglong2 q = vp[i]; vd[2*i] = q.x; vd[2*i+1] = q.y; }
                if (rr < 5) {
                    #pragma unroll
                    for (int o = 0; o < 5; o++) {
                        ull wd = wq[rr * 5 + o];
                        #pragma unroll
                        for (int xo = 0; xo < 8; xo++) pacc0[xo] = fma2(wd, vd[xo + o], pacc0[xo]);
                    }
                }
                if (rr >= 1) {
                    #pragma unroll
                    for (int o = 0; o < 5; o++) {
                        ull wd = wq[(rr - 1) * 5 + o];
                        #pragma unroll
                        for (int xo = 0; xo < 8; xo++) pacc1[xo] = fma2(wd, vd[xo + o], pacc1[xo]);
                    }
                }
            }
        }
    }

    int b0 = bq * 4 + pr * 2;
    #pragma unroll
    for (int X = 0; X < 4; X++) {
        float2 u0 = upk2(pacc0[2 * X]), u1 = upk2(pacc0[2 * X + 1]);
        float2 v0 = upk2(pacc1[2 * X]), v1 = upk2(pacc1[2 * X + 1]);
        float m0 = fmaxf(fmaxf(u0.x, u1.x), fmaxf(v0.x, v1.x));
        float m1 = fmaxf(fmaxf(u0.y, u1.y), fmaxf(v0.y, v1.y));
        ull pv = pk2(fmaxf(m0, 0.0f), fmaxf(m1, 0.0f));
        *(ull*)&g_h2T[((size_t)s * 800 + p * 16 + Y * 4 + X) * 32 + b0] = pv;
    }
}

// ---------------------------------------------------------------------------
// K3: fc1 (800->500)+relu -> g_h3P. grid (25 sg, 10 og), 320 thr (10 warps).
// Exact tiling: warp w handles o = obase + j*10 + w, j<5 (no idle warps).
// ---------------------------------------------------------------------------
#define FC1_SG 4
#define FC1_SMEM (FC1_SG * 80 * 64 * 4)
__global__ __launch_bounds__(320, 2) void k_fc1(const float* __restrict__ e) {
    extern __shared__ __align__(16) float sact[];   // [ss][m][b][2]
    int sg = blockIdx.x, og = blockIdx.y, t = threadIdx.x;
    int warp = t >> 5, lane = t & 31;
    int s0 = sg * FC1_SG;
    int obase = og * 50;
    const ull* sa = (const ull*)sact;

    ull acc[5][FC1_SG];
    #pragma unroll
    for (int j = 0; j < 5; j++)
        #pragma unroll
        for (int ss = 0; ss < FC1_SG; ss++) acc[j][ss] = 0ull;

    for (int c = 0; c < 5; c++) {
        __syncthreads();
        for (int u = t; u < FC1_SG * 80 * 8; u += 320) {
            int ss = u / 640, rem = u - ss * 640;
            int m = rem >> 3, b4 = (rem & 7) << 2;
            const float* src = g_h2T + (size_t)(s0 + ss) * 25600 + (size_t)(c * 160 + 2 * m) * 32 + b4;
            float4 r0 = *(const float4*)src;
            float4 r1 = *(const float4*)(src + 32);
            float* dst = sact + ((ss * 80 + m) * 32 + b4) * 2;
            ((float4*)dst)[0] = make_float4(r0.x, r1.x, r0.y, r1.y);
            ((float4*)dst)[1] = make_float4(r0.z, r1.z, r0.w, r1.w);
        }
        __syncthreads();

        #pragma unroll
        for (int j = 0; j < 5; j++) {
            int o = obase + j * 10 + warp;
            size_t ebase = 25570 + (size_t)o * 800 + c * 160;
            const ulonglong2* msq = ((const ulonglong2*)g_musp) + (ebase >> 1);
            const float* ep0 = e + (size_t)(s0 + 0) * EW + ebase;
            const float* ep1 = e + (size_t)(s0 + 1) * EW + ebase;
            const float* ep2 = e + (size_t)(s0 + 2) * EW + ebase;
            const float* ep3 = e + (size_t)(s0 + 3) * EW + ebase;
            const float* eps[FC1_SG] = {ep0, ep1, ep2, ep3};
            {   // head pair (local m=0)
                ulonglong2 qh = msq[0];
                #pragma unroll
                for (int ss = 0; ss < FC1_SG; ss++) {
                    ull ev = *(const ull*)(eps[ss]);
                    ull w = fma2(qh.y, ev, qh.x);
                    acc[j][ss] = fma2(w, sa[(ss * 80) * 32 + lane], acc[j][ss]);
                }
            }
            #pragma unroll 3
            for (int q = 0; q < 39; q++) {      // pairs 2q+1, 2q+2
                ulonglong2 q1 = msq[2 * q + 1];
                ulonglong2 q2 = msq[2 * q + 2];
                #pragma unroll
                for (int ss = 0; ss < FC1_SG; ss++) {
                    ulonglong2 ev = *(const ulonglong2*)(eps[ss] + 2 + 4 * q);
                    ull w1 = fma2(q1.y, ev.x, q1.x);
                    ull w2 = fma2(q2.y, ev.y, q2.x);
                    ull a = acc[j][ss];
                    a = fma2(w1, sa[(ss * 80 + 2 * q + 1) * 32 + lane], a);
                    a = fma2(w2, sa[(ss * 80 + 2 * q + 2) * 32 + lane], a);
                    acc[j][ss] = a;
                }
            }
            {   // tail pair (local m=79)
                ulonglong2 qt = msq[79];
                #pragma unroll
                for (int ss = 0; ss < FC1_SG; ss++) {
                    ull ev = *(const ull*)(eps[ss] + 158);
                    ull w = fma2(qt.y, ev, qt.x);
                    acc[j][ss] = fma2(w, sa[(ss * 80 + 79) * 32 + lane], acc[j][ss]);
                }
            }
        }
    }

    #pragma unroll
    for (int j = 0; j < 5; j++) {
        int o = obase + j * 10 + warp;
        #pragma unroll
        for (int ss = 0; ss < FC1_SG; ss++) {
            int s = s0 + ss;
            float2 u = upk2(acc[j][ss]);
            float bb = g_mu[425570 + o] + g_sp[425570 + o] * e[(size_t)s * EW + 425570 + o];
            g_h3P[(size_t)s * 16000 + (o >> 1) * 64 + lane * 2 + (o & 1)] =
                fmaxf(u.x + u.y + bb, 0.0f);
        }
    }
}

// ---------------------------------------------------------------------------
// K4: fc2 (500->10) -> g_logT. grid 100, 320 thr (warp = o).
// ---------------------------------------------------------------------------
__global__ void k_fc2(const float* __restrict__ e) {
    int s = blockIdx.x, t = threadIdx.x;
    int o = t >> 5, lane = t & 31;
    const float* es = e + (size_t)s * EW;
    const ulonglong2* ms = (const ulonglong2*)(g_musp + 2 * (size_t)(426070 + o * 500));
    const ull* e2 = (const ull*)(es + 426070 + o * 500);
    const ull* h2 = (const ull*)(g_h3P + (size_t)s * 16000);
    ull a = 0ull;
    #pragma unroll 5
    for (int q = 0; q < 250; q++) {
        ulonglong2 m = ms[q];
        ull w = fma2(m.y, e2[q], m.x);
        a = fma2(w, h2[q * 32 + lane], a);
    }
    float2 u = upk2(a);
    float bb = g_mu[431070 + o] + g_sp[431070 + o] * es[431070 + o];
    g_logT[((size_t)s * 10 + o) * 32 + lane] = u.x + u.y + bb;
}

// ---------------------------------------------------------------------------
// K5: log_softmax + mean over s -> out[b][10]. grid 32, 128 thr.
// ---------------------------------------------------------------------------
__global__ void k_final(float* __restrict__ out) {
    __shared__ float red[10 * 128];
    int b = blockIdx.x, t = threadIdx.x;
    float c[10];
    if (t < SS) {
        float v[10];
        float m = -1e30f;
        #pragma unroll
        for (int o = 0; o < 10; o++) {
            v[o] = g_logT[((size_t)t * 10 + o) * 32 + b];
            m = fmaxf(m, v[o]);
        }
        float se = 0.0f;
        #pragma unroll
        for (int o = 0; o < 10; o++) se += expf(v[o] - m);
        float lse = m + logf(se);
        #pragma unroll
        for (int o = 0; o < 10; o++) c[o] = v[o] - lse;
    } else {
        #pragma unroll
        for (int o = 0; o < 10; o++) c[o] = 0.0f;
    }
    #pragma unroll
    for (int o = 0; o < 10; o++) red[o * 128 + t] = c[o];
    __syncthreads();
    if (t < 10) {
        float sum = 0.0f;
        for (int i = 0; i < 128; i++) sum += red[t * 128 + i];
        out[b * 10 + t] = sum * (1.0f / SS);
    }
}

// ---------------------------------------------------------------------------
extern "C" void kernel_launch(void* const* d_in, const int* in_sizes, int n_in,
                              void* d_out, int out_size) {
    const float* x    = (const float*)d_in[0];
    const float* e    = (const float*)d_in[1];
    const float* c1mw = (const float*)d_in[2];
    const float* c1rw = (const float*)d_in[3];
    const float* c1mb = (const float*)d_in[4];
    const float* c1rb = (const float*)d_in[5];
    const float* c2mw = (const float*)d_in[6];
    const float* c2rw = (const float*)d_in[7];
    const float* c2mb = (const float*)d_in[8];
    const float* c2rb = (const float*)d_in[9];
    const float* a1mw = (const float*)d_in[10];
    const float* a1rw = (const float*)d_in[11];
    const float* a1mb = (const float*)d_in[12];
    const float* a1rb = (const float*)d_in[13];
    const float* a2mw = (const float*)d_in[14];
    const float* a2rw = (const float*)d_in[15];
    const float* a2mb = (const float*)d_in[16];
    const float* a2rb = (const float*)d_in[17];
    float* out = (float*)d_out;

    cudaFuncSetAttribute(k_conv2, cudaFuncAttributeMaxDynamicSharedMemorySize, CONV2_SMEM);
    cudaFuncSetAttribute(k_fc1,   cudaFuncAttributeMaxDynamicSharedMemorySize, FC1_SMEM);

    k_params<<<(EW + 255) / 256, 256>>>(c1mw, c1rw, c1mb, c1rb,
                                        c2mw, c2rw, c2mb, c2rb,
                                        a1mw, a1rw, a1mb, a1rb,
                                        a2mw, a2rw, a2mb, a2rb);
    k_w2<<<dim3(98, SS), 256>>>(e);
    k_conv1<<<dim3(SS, 16), 240>>>(x, e);
    k_conv2<<<dim3(SS, 8), 400, CONV2_SMEM>>>(e);
    k_fc1<<<dim3(25, 10), 320, FC1_SMEM>>>(e);
    k_fc2<<<SS, 320>>>(e);
    k_final<<<BB, 128>>>(out);
}